// round 12
// baseline (speedup 1.0000x reference)
#include <cuda_runtime.h>
#include <cuda_fp16.h>
#include <mma.h>
#include <math.h>
#include <stdint.h>

using namespace nvcuda;

// Problem constants
#define T_STEPS 256
#define BSZ     128
#define HID     512
#define MTOT    (T_STEPS * BSZ)                  // 32768
#define OUT_MAIN ((size_t)T_STEPS * BSZ * HID)   // 16777216
#define STATE_N  (BSZ * HID)                     // 65536

// ---------------------------------------------------------------------------
// Device scratch
// ---------------------------------------------------------------------------
__device__ __align__(256) __half g_xwh[4][(size_t)MTOT * 512];  // 128 MiB (fp16)
__device__ __align__(256) float g_u[4][STATE_N];                // cos values per step
__device__ __align__(256) __half g_hf[STATE_N];                 // h state, fp16

__device__ __align__(256) __half g_Xf[(size_t)MTOT * 512];
__device__ __align__(256) __half g_Wxf[4][512 * 512];
__device__ __align__(256) __half g_Whf[4][512 * 512];
__device__ __align__(256) unsigned g_bar4[4 * 32];

struct GateParams {
    const float* W[4];
    const float* b[4];
    const float* th[4];
};

// ---------------------------------------------------------------------------
// Conversions
// ---------------------------------------------------------------------------
__global__ __launch_bounds__(256) void convert_x(const float* __restrict__ X) {
    size_t i = ((size_t)blockIdx.x * blockDim.x + threadIdx.x) * 2;
    float2 v = *reinterpret_cast<const float2*>(X + i);
    *reinterpret_cast<__half2*>(&g_Xf[i]) = __floats2half2_rn(v.x, v.y);
}

__global__ __launch_bounds__(256) void convert_w(GateParams gp) {
    size_t i = ((size_t)blockIdx.x * blockDim.x + threadIdx.x) * 2;
    int g = (int)(i >> 19);
    size_t r = i & 524287;
    int n = (int)(r >> 10), k = (int)(r & 1023);
    float2 v = *reinterpret_cast<const float2*>(gp.W[g] + (size_t)n * 1024 + k);
    __half2 h = __floats2half2_rn(v.x, v.y);
    if (k < 512)
        *reinterpret_cast<__half2*>(&g_Wxf[g][(size_t)n * 512 + k]) = h;
    else
        *reinterpret_cast<__half2*>(&g_Whf[g][(size_t)n * 512 + (k - 512)]) = h;
}

// ===========================================================================
// Phase 1: fp16 WMMA, tile 128(m) x 64(n), K-chunk 64, 2-stage double buffer.
// 8 warps = 4(m) x 2(n); warp tile 32x32. 3 CTAs/SM (regs<=85, smem 55KB).
// ===========================================================================
#define SSTR1 72                        // 64 data + 8 pad halves
#define P1_STAGE 27648                  // (128+64) * 72 * 2 bytes

__global__ __launch_bounds__(256, 3) void phase1_wmma(GateParams gp) {
    extern __shared__ __align__(16) char smraw[];

    const int tid = threadIdx.x, wid = tid >> 5;
    const int g  = blockIdx.x >> 3;
    const int n0 = (blockIdx.x & 7) * 64;
    const int m0 = blockIdx.y * 128;
    const int wm = wid >> 1;
    const int wn = wid & 1;

    const uint32_t smaddr = (uint32_t)__cvta_generic_to_shared(smraw);

    // stage K-chunk c (64 wide): A 128x64 (1024 segs) + B 64x64 (512 segs)
    auto stage = [&](int c) {
        const int k0 = c * 64;
        const uint32_t base = smaddr + (uint32_t)(c & 1) * P1_STAGE;
#pragma unroll
        for (int it = 0; it < 6; it++) {
            int i = tid + it * 256;              // 0..1535
            if (i < 1024) {
                int r = i >> 3, s = i & 7;
                const __half* src = &g_Xf[(size_t)(m0 + r) * 512 + k0 + s * 8];
                asm volatile("cp.async.cg.shared.global [%0], [%1], 16;"
                    :: "r"(base + (uint32_t)(r * SSTR1 + s * 8) * 2), "l"(src) : "memory");
            } else {
                int j = i - 1024;
                int r = j >> 3, s = j & 7;
                const __half* src = &g_Wxf[g][(size_t)(n0 + r) * 512 + k0 + s * 8];
                asm volatile("cp.async.cg.shared.global [%0], [%1], 16;"
                    :: "r"(base + 18432u + (uint32_t)(r * SSTR1 + s * 8) * 2), "l"(src) : "memory");
            }
        }
        asm volatile("cp.async.commit_group;" ::: "memory");
    };

    wmma::fragment<wmma::accumulator, 16, 16, 16, float> acc[2][2];
#pragma unroll
    for (int i = 0; i < 2; i++)
#pragma unroll
        for (int j = 0; j < 2; j++) wmma::fill_fragment(acc[i][j], 0.0f);

    stage(0);
    for (int c = 0; c < 8; c++) {
        if (c < 7) {
            stage(c + 1);
            asm volatile("cp.async.wait_group 1;" ::: "memory");
        } else {
            asm volatile("cp.async.wait_group 0;" ::: "memory");
        }
        __syncthreads();
        const __half* sA = reinterpret_cast<const __half*>(smraw + (c & 1) * P1_STAGE);
        const __half* sB = sA + 128 * SSTR1;
#pragma unroll
        for (int kk = 0; kk < 64; kk += 16) {
            wmma::fragment<wmma::matrix_a, 16, 16, 16, __half, wmma::row_major> a[2];
            wmma::fragment<wmma::matrix_b, 16, 16, 16, __half, wmma::col_major> bfr[2];
#pragma unroll
            for (int i = 0; i < 2; i++)
                wmma::load_matrix_sync(a[i], &sA[(wm * 32 + i * 16) * SSTR1 + kk], SSTR1);
#pragma unroll
            for (int j = 0; j < 2; j++)
                wmma::load_matrix_sync(bfr[j], &sB[(wn * 32 + j * 16) * SSTR1 + kk], SSTR1);
#pragma unroll
            for (int i = 0; i < 2; i++)
#pragma unroll
                for (int j = 0; j < 2; j++)
                    wmma::mma_sync(acc[i][j], a[i], bfr[j], acc[i][j]);
        }
        __syncthreads();
    }

    // epilogue: single pass, 128 x 64 through smem (stride 68 floats)
    float* smf = reinterpret_cast<float*>(smraw);
    const float* __restrict__ bb = gp.b[g];
    const float* __restrict__ tt = gp.th[g];
#pragma unroll
    for (int i = 0; i < 2; i++)
#pragma unroll
        for (int j = 0; j < 2; j++)
            wmma::store_matrix_sync(&smf[(wm * 32 + i * 16) * 68 + wn * 32 + j * 16],
                                    acc[i][j], 68, wmma::mem_row_major);
    __syncthreads();
#pragma unroll
    for (int it = 0; it < 8; it++) {
        int i = tid + it * 256;            // 0..2047
        int r = i >> 4, c = (i & 15) * 4;
        int n = n0 + c;
        float4 v = *reinterpret_cast<const float4*>(&smf[r * 68 + c]);
        v.x += bb[n + 0] + tt[n + 0]; v.y += bb[n + 1] + tt[n + 1];
        v.z += bb[n + 2] + tt[n + 2]; v.w += bb[n + 3] + tt[n + 3];
        __half2 h01 = __floats2half2_rn(v.x, v.y);
        __half2 h23 = __floats2half2_rn(v.z, v.w);
        uint2 packed = make_uint2(*reinterpret_cast<uint32_t*>(&h01),
                                  *reinterpret_cast<uint32_t*>(&h23));
        *reinterpret_cast<uint2*>(&g_xwh[g][(size_t)(m0 + r) * 512 + n]) = packed;
    }
}

// ===========================================================================
// Persistent recurrence (R11 structure) + c-state in registers.
// ===========================================================================
#define HSTR 520

__device__ __forceinline__ void bar_arrive(unsigned* ctr) {
    asm volatile("red.release.gpu.global.add.u32 [%0], %1;"
                 :: "l"(ctr), "r"(1u) : "memory");
}
__device__ __forceinline__ void bar_spin(unsigned* ctr, unsigned target) {
    unsigned v;
    do {
        asm volatile("ld.acquire.gpu.global.u32 %0, [%1];"
                     : "=r"(v) : "l"(ctr) : "memory");
    } while (v < target);
}

__device__ __forceinline__ float fsig(float x) {
    float t = __expf(-x);
    return __fdividef(1.0f, 1.0f + t);
}
__device__ __forceinline__ float ftanh(float x) {
    float t = __expf(-2.0f * x);
    return __fdividef(1.0f - t, 1.0f + t);
}

__global__ __launch_bounds__(256, 1) void recurrence_persistent(float* __restrict__ out) {
    __shared__ __align__(16) __half sH[32 * HSTR];     // 33280 B
    __shared__ __align__(16) float su[32 * 68];        // 8704 B hv epilogue
    __shared__ __align__(16) __half sxw[32 * 64];      // 4096 B
    __shared__ float swt[8][4];

    const int tid = threadIdx.x, wid = tid >> 5, lane = tid & 31;
    const int cta = blockIdx.x;
    const int q   = cta >> 5;
    const int within = cta & 31;
    const int g  = within >> 3;
    const int nt = within & 7;
    const int n0 = nt * 64;
    const int b0 = q * 32;
    const int wm = wid & 1;
    const int wn = wid >> 1;
    const int b = cta;
    unsigned* ctr = &g_bar4[q * 32];

    const uint32_t sH_addr  = (uint32_t)__cvta_generic_to_shared(sH);
    const uint32_t sxw_addr = (uint32_t)__cvta_generic_to_shared(sxw);

    // c-state in registers (thread-private: k = tid*2 mapping is static)
    float creg0 = 0.f, creg1 = 0.f;

    // ---- Preload Wh fragments into registers (2 halves through sH) ----
    wmma::fragment<wmma::matrix_b, 16, 16, 16, __half, wmma::col_major> bfr[32];
#pragma unroll
    for (int half = 0; half < 2; half++) {
        __syncthreads();
#pragma unroll
        for (int it = 0; it < 8; it++) {
            int i = tid + it * 256;
            int r = i >> 6, s = i & 63;
            *reinterpret_cast<uint4*>(reinterpret_cast<char*>(sH) + (r * HSTR + s * 8) * 2) =
                *reinterpret_cast<const uint4*>(&g_Whf[g][(size_t)(n0 + half * 32 + r) * 512 + s * 8]);
        }
        __syncthreads();
        if ((wn >> 1) == half) {
            const int rloc = (wn & 1) * 16;
#pragma unroll
            for (int kk = 0; kk < 32; kk++)
                wmma::load_matrix_sync(bfr[kk], &sH[rloc * HSTR + kk * 16], HSTR);
        }
    }
    __syncthreads();

    auto stage_xw = [&](int t) {
        {
            int r = tid >> 3, s = tid & 7;
            const __half* src = &g_xwh[g][((size_t)t * BSZ + b0 + r) * 512 + n0 + s * 8];
            asm volatile("cp.async.cg.shared.global [%0], [%1], 16;"
                :: "r"(sxw_addr + (uint32_t)(r * 64 + s * 8) * 2), "l"(src) : "memory");
        }
        asm volatile("cp.async.commit_group;" ::: "memory");
    };

    stage_xw(0);

    for (int t = 0; t < T_STEPS; t++) {
        // ---- stage h tile in 2 K-halves
#pragma unroll
        for (int half = 0; half < 2; half++) {
#pragma unroll
            for (int it = 0; it < 4; it++) {
                int i = tid + it * 256;
                int r = i >> 5, s = (i & 31) + half * 32;
                const __half* src = &g_hf[(size_t)(b0 + r) * 512 + s * 8];
                asm volatile("cp.async.cg.shared.global [%0], [%1], 16;"
                    :: "r"(sH_addr + (uint32_t)(r * HSTR + s * 8) * 2), "l"(src) : "memory");
            }
            asm volatile("cp.async.commit_group;" ::: "memory");
        }

        wmma::fragment<wmma::accumulator, 16, 16, 16, float> acc0, acc1;
        wmma::fill_fragment(acc0, 0.0f);
        wmma::fill_fragment(acc1, 0.0f);

        asm volatile("cp.async.wait_group 1;" ::: "memory");
        __syncthreads();
#pragma unroll
        for (int kk = 0; kk < 16; kk += 2) {
            wmma::fragment<wmma::matrix_a, 16, 16, 16, __half, wmma::row_major> a0, a1;
            wmma::load_matrix_sync(a0, &sH[(wm * 16) * HSTR + kk * 16], HSTR);
            wmma::load_matrix_sync(a1, &sH[(wm * 16) * HSTR + (kk + 1) * 16], HSTR);
            wmma::mma_sync(acc0, a0, bfr[kk], acc0);
            wmma::mma_sync(acc1, a1, bfr[kk + 1], acc1);
        }
        asm volatile("cp.async.wait_group 0;" ::: "memory");
        __syncthreads();
#pragma unroll
        for (int kk = 16; kk < 32; kk += 2) {
            wmma::fragment<wmma::matrix_a, 16, 16, 16, __half, wmma::row_major> a0, a1;
            wmma::load_matrix_sync(a0, &sH[(wm * 16) * HSTR + kk * 16], HSTR);
            wmma::load_matrix_sync(a1, &sH[(wm * 16) * HSTR + (kk + 1) * 16], HSTR);
            wmma::mma_sync(acc0, a0, bfr[kk], acc0);
            wmma::mma_sync(acc1, a1, bfr[kk + 1], acc1);
        }
#pragma unroll
        for (int e = 0; e < acc0.num_elements; e++) acc0.x[e] += acc1.x[e];

        // ---- epilogue: dedicated su buffer
        wmma::store_matrix_sync(&su[(wm * 16) * 68 + wn * 16], acc0, 68,
                                wmma::mem_row_major);
        __syncthreads();
#pragma unroll
        for (int it = 0; it < 8; it++) {
            int i = tid + it * 256;
            int r = i >> 6, c = i & 63;
            float v = su[r * 68 + c] + __half2float(sxw[r * 64 + c]);
            g_u[g][(size_t)(b0 + r) * 512 + n0 + c] = __cosf(v);
        }
        // ---- barrier 1: arrive, hide xw(t+1) prefetch behind spin
        __syncthreads();
        if (tid == 0) bar_arrive(ctr);
        if (t + 1 < T_STEPS) stage_xw(t + 1);
        if (tid == 0) bar_spin(ctr, 32u * (2u * t + 1u));
        __syncthreads();

        // ---- Phase B: scan + gates for batch row b
        float h0, h1;
        size_t gidx;
        {
            const int k = tid * 2;
            const int idx = b * 512 + k;
            float c0[4], c1[4], inc[4];
#pragma unroll
            for (int qq = 0; qq < 4; qq++) {
                float2 uv = *reinterpret_cast<const float2*>(&g_u[qq][idx]);
                c0[qq] = uv.x; c1[qq] = uv.y;
                inc[qq] = c0[qq] * c1[qq];
            }

#pragma unroll
            for (int o = 1; o < 32; o <<= 1) {
#pragma unroll
                for (int qq = 0; qq < 4; qq++) {
                    float up = __shfl_up_sync(0xffffffffu, inc[qq], o);
                    if (lane >= o) inc[qq] *= up;
                }
            }
            float exc[4];
#pragma unroll
            for (int qq = 0; qq < 4; qq++) {
                float up = __shfl_up_sync(0xffffffffu, inc[qq], 1);
                exc[qq] = (lane == 0) ? 1.0f : up;
            }
            if (lane == 31) {
#pragma unroll
                for (int qq = 0; qq < 4; qq++) swt[wid][qq] = inc[qq];
            }
            __syncthreads();
            float pre[4] = {1.f, 1.f, 1.f, 1.f};
            for (int w = 0; w < wid; w++) {
#pragma unroll
                for (int qq = 0; qq < 4; qq++) pre[qq] *= swt[w][qq];
            }

            float P0[4], P1[4];
#pragma unroll
            for (int qq = 0; qq < 4; qq++) {
                float e = pre[qq] * exc[qq];
                P0[qq] = e * c0[qq];
                P1[qq] = P0[qq] * c1[qq];
            }

            float f0 = fsig(P0[0]), f1 = fsig(P1[0]);
            float i0 = fsig(P0[1]), i1 = fsig(P1[1]);
            float u0 = ftanh(P0[2]), u1 = ftanh(P1[2]);
            float o0 = fsig(P0[3]), o1 = fsig(P1[3]);

            creg0 = f0 * creg0 + i0 * u0;
            creg1 = f1 * creg1 + i1 * u1;
            h0 = o0 * ftanh(creg0);
            h1 = o1 * ftanh(creg1);

            gidx = (size_t)b * 512 + k;
            *reinterpret_cast<__half2*>(&g_hf[gidx]) = __floats2half2_rn(h0, h1);
        }
        // ---- barrier 2: arrive (orders h), hide out[] stores behind spin
        __syncthreads();
        if (tid == 0) bar_arrive(ctr);
        *reinterpret_cast<float2*>(&out[(size_t)t * STATE_N + gidx]) = make_float2(h0, h1);
        if (t == T_STEPS - 1) {
            *reinterpret_cast<float2*>(&out[OUT_MAIN + gidx]) = make_float2(h0, h1);
            *reinterpret_cast<float2*>(&out[OUT_MAIN + STATE_N + gidx]) =
                make_float2(creg0, creg1);
        }
        if (tid == 0) bar_spin(ctr, 32u * (2u * t + 2u));
        __syncthreads();
    }
}

// ===========================================================================
__global__ void init_state() {
    int i = blockIdx.x * blockDim.x + threadIdx.x;
    if (i < 4 * 32) g_bar4[i] = 0u;
    if (i < STATE_N) g_hf[i] = __float2half(0.f);
}

extern "C" void kernel_launch(void* const* d_in, const int* in_sizes, int n_in,
                              void* d_out, int out_size) {
    const float* X = (const float*)d_in[0];
    GateParams gp;
    for (int g = 0; g < 4; g++) {
        gp.W[g]  = (const float*)d_in[1 + 3 * g];
        gp.b[g]  = (const float*)d_in[2 + 3 * g];
        gp.th[g] = (const float*)d_in[3 + 3 * g];
    }
    float* out = (float*)d_out;

    init_state<<<(STATE_N + 255) / 256, 256>>>();

    convert_x<<<(MTOT * 512 / 2) / 256, 256>>>(X);
    convert_w<<<(4 * 512 * 1024 / 2) / 256, 256>>>(gp);

    const int p1_smem = 2 * P1_STAGE;   // 55296
    cudaFuncSetAttribute(phase1_wmma, cudaFuncAttributeMaxDynamicSharedMemorySize,
                         p1_smem);
    phase1_wmma<<<dim3(32, MTOT / 128), 256, p1_smem>>>(gp);

    recurrence_persistent<<<128, 256>>>(out);
}

// round 13
// speedup vs baseline: 1.0190x; 1.0190x over previous
#include <cuda_runtime.h>
#include <cuda_fp16.h>
#include <mma.h>
#include <math.h>
#include <stdint.h>

using namespace nvcuda;

// Problem constants
#define T_STEPS 256
#define BSZ     128
#define HID     512
#define MTOT    (T_STEPS * BSZ)                  // 32768
#define OUT_MAIN ((size_t)T_STEPS * BSZ * HID)   // 16777216
#define STATE_N  (BSZ * HID)                     // 65536

// ---------------------------------------------------------------------------
// Device scratch
// ---------------------------------------------------------------------------
__device__ __align__(256) __half g_xwh[4][(size_t)MTOT * 512];  // 128 MiB (fp16)
__device__ __align__(256) float g_u[4][STATE_N];                // cos values per step
__device__ __align__(256) __half g_hf[STATE_N];                 // h state, fp16

__device__ __align__(256) __half g_Xf[(size_t)MTOT * 512];
__device__ __align__(256) __half g_Wxf[4][512 * 512];
__device__ __align__(256) __half g_Whf[4][512 * 512];
__device__ __align__(256) unsigned g_bar4[4 * 32];

struct GateParams {
    const float* W[4];
    const float* b[4];
    const float* th[4];
};

// ---------------------------------------------------------------------------
// Conversions
// ---------------------------------------------------------------------------
__global__ __launch_bounds__(256) void convert_x(const float* __restrict__ X) {
    size_t i = ((size_t)blockIdx.x * blockDim.x + threadIdx.x) * 2;
    float2 v = *reinterpret_cast<const float2*>(X + i);
    *reinterpret_cast<__half2*>(&g_Xf[i]) = __floats2half2_rn(v.x, v.y);
}

__global__ __launch_bounds__(256) void convert_w(GateParams gp) {
    size_t i = ((size_t)blockIdx.x * blockDim.x + threadIdx.x) * 2;
    int g = (int)(i >> 19);
    size_t r = i & 524287;
    int n = (int)(r >> 10), k = (int)(r & 1023);
    float2 v = *reinterpret_cast<const float2*>(gp.W[g] + (size_t)n * 1024 + k);
    __half2 h = __floats2half2_rn(v.x, v.y);
    if (k < 512)
        *reinterpret_cast<__half2*>(&g_Wxf[g][(size_t)n * 512 + k]) = h;
    else
        *reinterpret_cast<__half2*>(&g_Whf[g][(size_t)n * 512 + (k - 512)]) = h;
}

// ===========================================================================
// Phase 1 (R11 best configuration): fp16 WMMA, tile 128(m) x 128(n),
// K-chunk 64, 2-stage double buffer. 8 warps = 4(m) x 2(n).
// smem 2 x 36864 = 73728 B.
// ===========================================================================
#define SSTR1 72                        // 64 data + 8 pad halves
#define P1_STAGE 36864                  // (128+128) * 72 * 2 bytes

__global__ __launch_bounds__(256) void phase1_wmma(GateParams gp) {
    extern __shared__ __align__(16) char smraw[];

    const int tid = threadIdx.x, wid = tid >> 5;
    const int nt = blockIdx.x;
    const int g  = nt >> 2;
    const int n0 = (nt & 3) * 128;
    const int m0 = blockIdx.y * 128;
    const int wm = wid >> 1;
    const int wn = wid & 1;

    const uint32_t smaddr = (uint32_t)__cvta_generic_to_shared(smraw);

    // stage K-chunk c (64 wide): A 128x64 + B 128x64 halves = 2048 x 16B
    auto stage = [&](int c) {
        const int k0 = c * 64;
        const uint32_t base = smaddr + (uint32_t)(c & 1) * P1_STAGE;
#pragma unroll
        for (int it = 0; it < 8; it++) {
            int i = tid + it * 256;              // 0..2047
            int mat = i >> 10;                   // 0 = A(X), 1 = B(W)
            int r = (i >> 3) & 127, s = i & 7;   // 8 x 16B segs per row
            const __half* src = mat
                ? &g_Wxf[g][(size_t)(n0 + r) * 512 + k0 + s * 8]
                : &g_Xf[(size_t)(m0 + r) * 512 + k0 + s * 8];
            asm volatile("cp.async.cg.shared.global [%0], [%1], 16;"
                :: "r"(base + (uint32_t)mat * 18432 + (uint32_t)(r * SSTR1 + s * 8) * 2),
                   "l"(src) : "memory");
        }
        asm volatile("cp.async.commit_group;" ::: "memory");
    };

    wmma::fragment<wmma::accumulator, 16, 16, 16, float> acc[2][4];
#pragma unroll
    for (int i = 0; i < 2; i++)
#pragma unroll
        for (int j = 0; j < 4; j++) wmma::fill_fragment(acc[i][j], 0.0f);

    stage(0);
    for (int c = 0; c < 8; c++) {
        if (c < 7) {
            stage(c + 1);
            asm volatile("cp.async.wait_group 1;" ::: "memory");
        } else {
            asm volatile("cp.async.wait_group 0;" ::: "memory");
        }
        __syncthreads();
        const __half* sA = reinterpret_cast<const __half*>(smraw + (c & 1) * P1_STAGE);
        const __half* sB = sA + 128 * SSTR1;
#pragma unroll
        for (int kk = 0; kk < 64; kk += 16) {
            wmma::fragment<wmma::matrix_a, 16, 16, 16, __half, wmma::row_major> a[2];
            wmma::fragment<wmma::matrix_b, 16, 16, 16, __half, wmma::col_major> bfr[4];
#pragma unroll
            for (int i = 0; i < 2; i++)
                wmma::load_matrix_sync(a[i], &sA[(wm * 32 + i * 16) * SSTR1 + kk], SSTR1);
#pragma unroll
            for (int j = 0; j < 4; j++)
                wmma::load_matrix_sync(bfr[j], &sB[(wn * 64 + j * 16) * SSTR1 + kk], SSTR1);
#pragma unroll
            for (int i = 0; i < 2; i++)
#pragma unroll
                for (int j = 0; j < 4; j++)
                    wmma::mma_sync(acc[i][j], a[i], bfr[j], acc[i][j]);
        }
        __syncthreads();
    }

    float* smf = reinterpret_cast<float*>(smraw);
    const float* __restrict__ bb = gp.b[g];
    const float* __restrict__ tt = gp.th[g];
#pragma unroll
    for (int half = 0; half < 2; half++) {
        if (wn == half) {
#pragma unroll
            for (int i = 0; i < 2; i++)
#pragma unroll
                for (int j = 0; j < 4; j++)
                    wmma::store_matrix_sync(&smf[(wm * 32 + i * 16) * 68 + j * 16],
                                            acc[i][j], 68, wmma::mem_row_major);
        }
        __syncthreads();
#pragma unroll
        for (int it = 0; it < 8; it++) {
            int i = tid + it * 256;
            int r = i >> 4, c = (i & 15) * 4;
            int n = n0 + half * 64 + c;
            float4 v = *reinterpret_cast<const float4*>(&smf[r * 68 + c]);
            v.x += bb[n + 0] + tt[n + 0]; v.y += bb[n + 1] + tt[n + 1];
            v.z += bb[n + 2] + tt[n + 2]; v.w += bb[n + 3] + tt[n + 3];
            __half2 h01 = __floats2half2_rn(v.x, v.y);
            __half2 h23 = __floats2half2_rn(v.z, v.w);
            uint2 packed = make_uint2(*reinterpret_cast<uint32_t*>(&h01),
                                      *reinterpret_cast<uint32_t*>(&h23));
            *reinterpret_cast<uint2*>(&g_xwh[g][(size_t)(m0 + r) * 512 + n]) = packed;
        }
        __syncthreads();
    }
}

// ===========================================================================
// Persistent recurrence (R10/R11 structure) + c-state in registers.
// ===========================================================================
#define HSTR 520

__device__ __forceinline__ void bar_arrive(unsigned* ctr) {
    asm volatile("red.release.gpu.global.add.u32 [%0], %1;"
                 :: "l"(ctr), "r"(1u) : "memory");
}
__device__ __forceinline__ void bar_spin(unsigned* ctr, unsigned target) {
    unsigned v;
    do {
        asm volatile("ld.acquire.gpu.global.u32 %0, [%1];"
                     : "=r"(v) : "l"(ctr) : "memory");
    } while (v < target);
}

__device__ __forceinline__ float fsig(float x) {
    float t = __expf(-x);
    return __fdividef(1.0f, 1.0f + t);
}
__device__ __forceinline__ float ftanh(float x) {
    float t = __expf(-2.0f * x);
    return __fdividef(1.0f - t, 1.0f + t);
}

__global__ __launch_bounds__(256, 1) void recurrence_persistent(float* __restrict__ out) {
    __shared__ __align__(16) __half sH[32 * HSTR];     // 33280 B
    __shared__ __align__(16) float su[32 * 68];        // 8704 B hv epilogue
    __shared__ __align__(16) __half sxw[32 * 64];      // 4096 B
    __shared__ float swt[8][4];

    const int tid = threadIdx.x, wid = tid >> 5, lane = tid & 31;
    const int cta = blockIdx.x;
    const int q   = cta >> 5;
    const int within = cta & 31;
    const int g  = within >> 3;
    const int nt = within & 7;
    const int n0 = nt * 64;
    const int b0 = q * 32;
    const int wm = wid & 1;
    const int wn = wid >> 1;
    const int b = cta;
    unsigned* ctr = &g_bar4[q * 32];

    const uint32_t sH_addr  = (uint32_t)__cvta_generic_to_shared(sH);
    const uint32_t sxw_addr = (uint32_t)__cvta_generic_to_shared(sxw);

    // c-state in registers (thread-private: k = tid*2 mapping is static)
    float creg0 = 0.f, creg1 = 0.f;

    // ---- Preload Wh fragments into registers (2 halves through sH) ----
    wmma::fragment<wmma::matrix_b, 16, 16, 16, __half, wmma::col_major> bfr[32];
#pragma unroll
    for (int half = 0; half < 2; half++) {
        __syncthreads();
#pragma unroll
        for (int it = 0; it < 8; it++) {
            int i = tid + it * 256;
            int r = i >> 6, s = i & 63;
            *reinterpret_cast<uint4*>(reinterpret_cast<char*>(sH) + (r * HSTR + s * 8) * 2) =
                *reinterpret_cast<const uint4*>(&g_Whf[g][(size_t)(n0 + half * 32 + r) * 512 + s * 8]);
        }
        __syncthreads();
        if ((wn >> 1) == half) {
            const int rloc = (wn & 1) * 16;
#pragma unroll
            for (int kk = 0; kk < 32; kk++)
                wmma::load_matrix_sync(bfr[kk], &sH[rloc * HSTR + kk * 16], HSTR);
        }
    }
    __syncthreads();

    auto stage_xw = [&](int t) {
        {
            int r = tid >> 3, s = tid & 7;
            const __half* src = &g_xwh[g][((size_t)t * BSZ + b0 + r) * 512 + n0 + s * 8];
            asm volatile("cp.async.cg.shared.global [%0], [%1], 16;"
                :: "r"(sxw_addr + (uint32_t)(r * 64 + s * 8) * 2), "l"(src) : "memory");
        }
        asm volatile("cp.async.commit_group;" ::: "memory");
    };

    stage_xw(0);

    for (int t = 0; t < T_STEPS; t++) {
        // ---- stage h tile in 2 K-halves
#pragma unroll
        for (int half = 0; half < 2; half++) {
#pragma unroll
            for (int it = 0; it < 4; it++) {
                int i = tid + it * 256;
                int r = i >> 5, s = (i & 31) + half * 32;
                const __half* src = &g_hf[(size_t)(b0 + r) * 512 + s * 8];
                asm volatile("cp.async.cg.shared.global [%0], [%1], 16;"
                    :: "r"(sH_addr + (uint32_t)(r * HSTR + s * 8) * 2), "l"(src) : "memory");
            }
            asm volatile("cp.async.commit_group;" ::: "memory");
        }

        wmma::fragment<wmma::accumulator, 16, 16, 16, float> acc0, acc1;
        wmma::fill_fragment(acc0, 0.0f);
        wmma::fill_fragment(acc1, 0.0f);

        asm volatile("cp.async.wait_group 1;" ::: "memory");
        __syncthreads();
#pragma unroll
        for (int kk = 0; kk < 16; kk += 2) {
            wmma::fragment<wmma::matrix_a, 16, 16, 16, __half, wmma::row_major> a0, a1;
            wmma::load_matrix_sync(a0, &sH[(wm * 16) * HSTR + kk * 16], HSTR);
            wmma::load_matrix_sync(a1, &sH[(wm * 16) * HSTR + (kk + 1) * 16], HSTR);
            wmma::mma_sync(acc0, a0, bfr[kk], acc0);
            wmma::mma_sync(acc1, a1, bfr[kk + 1], acc1);
        }
        asm volatile("cp.async.wait_group 0;" ::: "memory");
        __syncthreads();
#pragma unroll
        for (int kk = 16; kk < 32; kk += 2) {
            wmma::fragment<wmma::matrix_a, 16, 16, 16, __half, wmma::row_major> a0, a1;
            wmma::load_matrix_sync(a0, &sH[(wm * 16) * HSTR + kk * 16], HSTR);
            wmma::load_matrix_sync(a1, &sH[(wm * 16) * HSTR + (kk + 1) * 16], HSTR);
            wmma::mma_sync(acc0, a0, bfr[kk], acc0);
            wmma::mma_sync(acc1, a1, bfr[kk + 1], acc1);
        }
#pragma unroll
        for (int e = 0; e < acc0.num_elements; e++) acc0.x[e] += acc1.x[e];

        // ---- epilogue: dedicated su buffer
        wmma::store_matrix_sync(&su[(wm * 16) * 68 + wn * 16], acc0, 68,
                                wmma::mem_row_major);
        __syncthreads();
#pragma unroll
        for (int it = 0; it < 8; it++) {
            int i = tid + it * 256;
            int r = i >> 6, c = i & 63;
            float v = su[r * 68 + c] + __half2float(sxw[r * 64 + c]);
            g_u[g][(size_t)(b0 + r) * 512 + n0 + c] = __cosf(v);
        }
        // ---- barrier 1: arrive, hide xw(t+1) prefetch behind spin
        __syncthreads();
        if (tid == 0) bar_arrive(ctr);
        if (t + 1 < T_STEPS) stage_xw(t + 1);
        if (tid == 0) bar_spin(ctr, 32u * (2u * t + 1u));
        __syncthreads();

        // ---- Phase B: scan + gates for batch row b
        float h0, h1;
        size_t gidx;
        {
            const int k = tid * 2;
            const int idx = b * 512 + k;
            float c0[4], c1[4], inc[4];
#pragma unroll
            for (int qq = 0; qq < 4; qq++) {
                float2 uv = *reinterpret_cast<const float2*>(&g_u[qq][idx]);
                c0[qq] = uv.x; c1[qq] = uv.y;
                inc[qq] = c0[qq] * c1[qq];
            }

#pragma unroll
            for (int o = 1; o < 32; o <<= 1) {
#pragma unroll
                for (int qq = 0; qq < 4; qq++) {
                    float up = __shfl_up_sync(0xffffffffu, inc[qq], o);
                    if (lane >= o) inc[qq] *= up;
                }
            }
            float exc[4];
#pragma unroll
            for (int qq = 0; qq < 4; qq++) {
                float up = __shfl_up_sync(0xffffffffu, inc[qq], 1);
                exc[qq] = (lane == 0) ? 1.0f : up;
            }
            if (lane == 31) {
#pragma unroll
                for (int qq = 0; qq < 4; qq++) swt[wid][qq] = inc[qq];
            }
            __syncthreads();
            float pre[4] = {1.f, 1.f, 1.f, 1.f};
            for (int w = 0; w < wid; w++) {
#pragma unroll
                for (int qq = 0; qq < 4; qq++) pre[qq] *= swt[w][qq];
            }

            float P0[4], P1[4];
#pragma unroll
            for (int qq = 0; qq < 4; qq++) {
                float e = pre[qq] * exc[qq];
                P0[qq] = e * c0[qq];
                P1[qq] = P0[qq] * c1[qq];
            }

            float f0 = fsig(P0[0]), f1 = fsig(P1[0]);
            float i0 = fsig(P0[1]), i1 = fsig(P1[1]);
            float u0 = ftanh(P0[2]), u1 = ftanh(P1[2]);
            float o0 = fsig(P0[3]), o1 = fsig(P1[3]);

            creg0 = f0 * creg0 + i0 * u0;
            creg1 = f1 * creg1 + i1 * u1;
            h0 = o0 * ftanh(creg0);
            h1 = o1 * ftanh(creg1);

            gidx = (size_t)b * 512 + k;
            *reinterpret_cast<__half2*>(&g_hf[gidx]) = __floats2half2_rn(h0, h1);
        }
        // ---- barrier 2: arrive (orders h), hide out[] stores behind spin
        __syncthreads();
        if (tid == 0) bar_arrive(ctr);
        *reinterpret_cast<float2*>(&out[(size_t)t * STATE_N + gidx]) = make_float2(h0, h1);
        if (t == T_STEPS - 1) {
            *reinterpret_cast<float2*>(&out[OUT_MAIN + gidx]) = make_float2(h0, h1);
            *reinterpret_cast<float2*>(&out[OUT_MAIN + STATE_N + gidx]) =
                make_float2(creg0, creg1);
        }
        if (tid == 0) bar_spin(ctr, 32u * (2u * t + 2u));
        __syncthreads();
    }
}

// ===========================================================================
__global__ void init_state() {
    int i = blockIdx.x * blockDim.x + threadIdx.x;
    if (i < 4 * 32) g_bar4[i] = 0u;
    if (i < STATE_N) g_hf[i] = __float2half(0.f);
}

extern "C" void kernel_launch(void* const* d_in, const int* in_sizes, int n_in,
                              void* d_out, int out_size) {
    const float* X = (const float*)d_in[0];
    GateParams gp;
    for (int g = 0; g < 4; g++) {
        gp.W[g]  = (const float*)d_in[1 + 3 * g];
        gp.b[g]  = (const float*)d_in[2 + 3 * g];
        gp.th[g] = (const float*)d_in[3 + 3 * g];
    }
    float* out = (float*)d_out;

    init_state<<<(STATE_N + 255) / 256, 256>>>();

    convert_x<<<(MTOT * 512 / 2) / 256, 256>>>(X);
    convert_w<<<(4 * 512 * 1024 / 2) / 256, 256>>>(gp);

    const int p1_smem = 2 * P1_STAGE;   // 73728
    cudaFuncSetAttribute(phase1_wmma, cudaFuncAttributeMaxDynamicSharedMemorySize,
                         p1_smem);
    phase1_wmma<<<dim3(16, MTOT / 128), 256, p1_smem>>>(gp);

    recurrence_persistent<<<128, 256>>>(out);
}

// round 14
// speedup vs baseline: 1.0190x; 1.0000x over previous
#include <cuda_runtime.h>
#include <cuda_fp16.h>
#include <mma.h>
#include <math.h>
#include <stdint.h>

using namespace nvcuda;

// Problem constants
#define T_STEPS 256
#define BSZ     128
#define HID     512
#define MTOT    (T_STEPS * BSZ)                  // 32768
#define OUT_MAIN ((size_t)T_STEPS * BSZ * HID)   // 16777216
#define STATE_N  (BSZ * HID)                     // 65536

// ---------------------------------------------------------------------------
// Device scratch
// ---------------------------------------------------------------------------
__device__ __align__(256) __half g_xwh[4][(size_t)MTOT * 512];  // 128 MiB (fp16)
__device__ __align__(256) float g_u[4][STATE_N];                // cos values per step
__device__ __align__(256) __half g_hf[STATE_N];                 // h state, fp16

__device__ __align__(256) __half g_Xf[(size_t)MTOT * 512];
__device__ __align__(256) __half g_Wxf[4][512 * 512];
__device__ __align__(256) __half g_Whf[4][512 * 512];
__device__ __align__(256) unsigned g_bar4[4 * 32];

struct GateParams {
    const float* W[4];
    const float* b[4];
    const float* th[4];
};

// ---------------------------------------------------------------------------
// Conversions (convert_x also performs state init: saves one launch)
// ---------------------------------------------------------------------------
__global__ __launch_bounds__(256) void convert_x(const float* __restrict__ X) {
    size_t i = ((size_t)blockIdx.x * blockDim.x + threadIdx.x) * 2;
    float2 v = *reinterpret_cast<const float2*>(X + i);
    *reinterpret_cast<__half2*>(&g_Xf[i]) = __floats2half2_rn(v.x, v.y);

    // fold state init into the first blocks
    size_t j = (size_t)blockIdx.x * blockDim.x + threadIdx.x;
    if (j < STATE_N)
        *reinterpret_cast<__half2*>(&g_hf[j * 2]) = __floats2half2_rn(0.f, 0.f);
    if (j < 4 * 32) g_bar4[j] = 0u;
}

__global__ __launch_bounds__(256) void convert_w(GateParams gp) {
    size_t i = ((size_t)blockIdx.x * blockDim.x + threadIdx.x) * 2;
    int g = (int)(i >> 19);
    size_t r = i & 524287;
    int n = (int)(r >> 10), k = (int)(r & 1023);
    float2 v = *reinterpret_cast<const float2*>(gp.W[g] + (size_t)n * 1024 + k);
    __half2 h = __floats2half2_rn(v.x, v.y);
    if (k < 512)
        *reinterpret_cast<__half2*>(&g_Wxf[g][(size_t)n * 512 + k]) = h;
    else
        *reinterpret_cast<__half2*>(&g_Whf[g][(size_t)n * 512 + (k - 512)]) = h;
}

// ===========================================================================
// Phase 1: fp16 WMMA, tile 128(m) x 128(n), K-chunk 64, double buffer,
// single-pass epilogue (128 x 132-float smem tile).
// ===========================================================================
#define SSTR1 72                        // 64 data + 8 pad halves
#define P1_STAGE 36864                  // (128+128) * 72 * 2 bytes
#define ESTR 132                        // epilogue float stride

__global__ __launch_bounds__(256) void phase1_wmma(GateParams gp) {
    extern __shared__ __align__(16) char smraw[];

    const int tid = threadIdx.x, wid = tid >> 5;
    const int nt = blockIdx.x;
    const int g  = nt >> 2;
    const int n0 = (nt & 3) * 128;
    const int m0 = blockIdx.y * 128;
    const int wm = wid >> 1;
    const int wn = wid & 1;

    const uint32_t smaddr = (uint32_t)__cvta_generic_to_shared(smraw);

    // stage K-chunk c (64 wide): A 128x64 + B 128x64 halves = 2048 x 16B
    auto stage = [&](int c) {
        const int k0 = c * 64;
        const uint32_t base = smaddr + (uint32_t)(c & 1) * P1_STAGE;
#pragma unroll
        for (int it = 0; it < 8; it++) {
            int i = tid + it * 256;              // 0..2047
            int mat = i >> 10;                   // 0 = A(X), 1 = B(W)
            int r = (i >> 3) & 127, s = i & 7;   // 8 x 16B segs per row
            const __half* src = mat
                ? &g_Wxf[g][(size_t)(n0 + r) * 512 + k0 + s * 8]
                : &g_Xf[(size_t)(m0 + r) * 512 + k0 + s * 8];
            asm volatile("cp.async.cg.shared.global [%0], [%1], 16;"
                :: "r"(base + (uint32_t)mat * 18432 + (uint32_t)(r * SSTR1 + s * 8) * 2),
                   "l"(src) : "memory");
        }
        asm volatile("cp.async.commit_group;" ::: "memory");
    };

    wmma::fragment<wmma::accumulator, 16, 16, 16, float> acc[2][4];
#pragma unroll
    for (int i = 0; i < 2; i++)
#pragma unroll
        for (int j = 0; j < 4; j++) wmma::fill_fragment(acc[i][j], 0.0f);

    stage(0);
    for (int c = 0; c < 8; c++) {
        if (c < 7) {
            stage(c + 1);
            asm volatile("cp.async.wait_group 1;" ::: "memory");
        } else {
            asm volatile("cp.async.wait_group 0;" ::: "memory");
        }
        __syncthreads();
        const __half* sA = reinterpret_cast<const __half*>(smraw + (c & 1) * P1_STAGE);
        const __half* sB = sA + 128 * SSTR1;
#pragma unroll
        for (int kk = 0; kk < 64; kk += 16) {
            wmma::fragment<wmma::matrix_a, 16, 16, 16, __half, wmma::row_major> a[2];
            wmma::fragment<wmma::matrix_b, 16, 16, 16, __half, wmma::col_major> bfr[4];
#pragma unroll
            for (int i = 0; i < 2; i++)
                wmma::load_matrix_sync(a[i], &sA[(wm * 32 + i * 16) * SSTR1 + kk], SSTR1);
#pragma unroll
            for (int j = 0; j < 4; j++)
                wmma::load_matrix_sync(bfr[j], &sB[(wn * 64 + j * 16) * SSTR1 + kk], SSTR1);
#pragma unroll
            for (int i = 0; i < 2; i++)
#pragma unroll
                for (int j = 0; j < 4; j++)
                    wmma::mma_sync(acc[i][j], a[i], bfr[j], acc[i][j]);
        }
        __syncthreads();
    }

    // ---- single-pass epilogue: 128 x 128 through smem (stride 132 floats)
    float* smf = reinterpret_cast<float*>(smraw);
#pragma unroll
    for (int i = 0; i < 2; i++)
#pragma unroll
        for (int j = 0; j < 4; j++)
            wmma::store_matrix_sync(&smf[(wm * 32 + i * 16) * ESTR + wn * 64 + j * 16],
                                    acc[i][j], ESTR, wmma::mem_row_major);
    __syncthreads();
    const float* __restrict__ bb = gp.b[g];
    const float* __restrict__ tt = gp.th[g];
#pragma unroll
    for (int it = 0; it < 16; it++) {
        int i = tid + it * 256;             // 0..4095
        int r = i >> 5, c = (i & 31) * 4;
        int n = n0 + c;
        float4 v = *reinterpret_cast<const float4*>(&smf[r * ESTR + c]);
        v.x += bb[n + 0] + tt[n + 0]; v.y += bb[n + 1] + tt[n + 1];
        v.z += bb[n + 2] + tt[n + 2]; v.w += bb[n + 3] + tt[n + 3];
        __half2 h01 = __floats2half2_rn(v.x, v.y);
        __half2 h23 = __floats2half2_rn(v.z, v.w);
        uint2 packed = make_uint2(*reinterpret_cast<uint32_t*>(&h01),
                                  *reinterpret_cast<uint32_t*>(&h23));
        *reinterpret_cast<uint2*>(&g_xwh[g][(size_t)(m0 + r) * 512 + n]) = packed;
    }
}

// ===========================================================================
// Persistent recurrence (best-known R10/R13 structure, c-state in registers)
// ===========================================================================
#define HSTR 520

__device__ __forceinline__ void bar_arrive(unsigned* ctr) {
    asm volatile("red.release.gpu.global.add.u32 [%0], %1;"
                 :: "l"(ctr), "r"(1u) : "memory");
}
__device__ __forceinline__ void bar_spin(unsigned* ctr, unsigned target) {
    unsigned v;
    do {
        asm volatile("ld.acquire.gpu.global.u32 %0, [%1];"
                     : "=r"(v) : "l"(ctr) : "memory");
    } while (v < target);
}

__device__ __forceinline__ float fsig(float x) {
    float t = __expf(-x);
    return __fdividef(1.0f, 1.0f + t);
}
__device__ __forceinline__ float ftanh(float x) {
    float t = __expf(-2.0f * x);
    return __fdividef(1.0f - t, 1.0f + t);
}

__global__ __launch_bounds__(256, 1) void recurrence_persistent(float* __restrict__ out) {
    __shared__ __align__(16) __half sH[32 * HSTR];     // 33280 B
    __shared__ __align__(16) float su[32 * 68];        // 8704 B hv epilogue
    __shared__ __align__(16) __half sxw[32 * 64];      // 4096 B
    __shared__ float swt[8][4];

    const int tid = threadIdx.x, wid = tid >> 5, lane = tid & 31;
    const int cta = blockIdx.x;
    const int q   = cta >> 5;
    const int within = cta & 31;
    const int g  = within >> 3;
    const int nt = within & 7;
    const int n0 = nt * 64;
    const int b0 = q * 32;
    const int wm = wid & 1;
    const int wn = wid >> 1;
    const int b = cta;
    unsigned* ctr = &g_bar4[q * 32];

    const uint32_t sH_addr  = (uint32_t)__cvta_generic_to_shared(sH);
    const uint32_t sxw_addr = (uint32_t)__cvta_generic_to_shared(sxw);

    // c-state in registers (thread-private: k = tid*2 mapping is static)
    float creg0 = 0.f, creg1 = 0.f;

    // ---- Preload Wh fragments into registers (2 halves through sH) ----
    wmma::fragment<wmma::matrix_b, 16, 16, 16, __half, wmma::col_major> bfr[32];
#pragma unroll
    for (int half = 0; half < 2; half++) {
        __syncthreads();
#pragma unroll
        for (int it = 0; it < 8; it++) {
            int i = tid + it * 256;
            int r = i >> 6, s = i & 63;
            *reinterpret_cast<uint4*>(reinterpret_cast<char*>(sH) + (r * HSTR + s * 8) * 2) =
                *reinterpret_cast<const uint4*>(&g_Whf[g][(size_t)(n0 + half * 32 + r) * 512 + s * 8]);
        }
        __syncthreads();
        if ((wn >> 1) == half) {
            const int rloc = (wn & 1) * 16;
#pragma unroll
            for (int kk = 0; kk < 32; kk++)
                wmma::load_matrix_sync(bfr[kk], &sH[rloc * HSTR + kk * 16], HSTR);
        }
    }
    __syncthreads();

    auto stage_xw = [&](int t) {
        {
            int r = tid >> 3, s = tid & 7;
            const __half* src = &g_xwh[g][((size_t)t * BSZ + b0 + r) * 512 + n0 + s * 8];
            asm volatile("cp.async.cg.shared.global [%0], [%1], 16;"
                :: "r"(sxw_addr + (uint32_t)(r * 64 + s * 8) * 2), "l"(src) : "memory");
        }
        asm volatile("cp.async.commit_group;" ::: "memory");
    };

    stage_xw(0);

    for (int t = 0; t < T_STEPS; t++) {
        // ---- stage h tile in 2 K-halves
#pragma unroll
        for (int half = 0; half < 2; half++) {
#pragma unroll
            for (int it = 0; it < 4; it++) {
                int i = tid + it * 256;
                int r = i >> 5, s = (i & 31) + half * 32;
                const __half* src = &g_hf[(size_t)(b0 + r) * 512 + s * 8];
                asm volatile("cp.async.cg.shared.global [%0], [%1], 16;"
                    :: "r"(sH_addr + (uint32_t)(r * HSTR + s * 8) * 2), "l"(src) : "memory");
            }
            asm volatile("cp.async.commit_group;" ::: "memory");
        }

        wmma::fragment<wmma::accumulator, 16, 16, 16, float> acc0, acc1;
        wmma::fill_fragment(acc0, 0.0f);
        wmma::fill_fragment(acc1, 0.0f);

        asm volatile("cp.async.wait_group 1;" ::: "memory");
        __syncthreads();
#pragma unroll
        for (int kk = 0; kk < 16; kk += 2) {
            wmma::fragment<wmma::matrix_a, 16, 16, 16, __half, wmma::row_major> a0, a1;
            wmma::load_matrix_sync(a0, &sH[(wm * 16) * HSTR + kk * 16], HSTR);
            wmma::load_matrix_sync(a1, &sH[(wm * 16) * HSTR + (kk + 1) * 16], HSTR);
            wmma::mma_sync(acc0, a0, bfr[kk], acc0);
            wmma::mma_sync(acc1, a1, bfr[kk + 1], acc1);
        }
        asm volatile("cp.async.wait_group 0;" ::: "memory");
        __syncthreads();
#pragma unroll
        for (int kk = 16; kk < 32; kk += 2) {
            wmma::fragment<wmma::matrix_a, 16, 16, 16, __half, wmma::row_major> a0, a1;
            wmma::load_matrix_sync(a0, &sH[(wm * 16) * HSTR + kk * 16], HSTR);
            wmma::load_matrix_sync(a1, &sH[(wm * 16) * HSTR + (kk + 1) * 16], HSTR);
            wmma::mma_sync(acc0, a0, bfr[kk], acc0);
            wmma::mma_sync(acc1, a1, bfr[kk + 1], acc1);
        }
#pragma unroll
        for (int e = 0; e < acc0.num_elements; e++) acc0.x[e] += acc1.x[e];

        // ---- epilogue: dedicated su buffer
        wmma::store_matrix_sync(&su[(wm * 16) * 68 + wn * 16], acc0, 68,
                                wmma::mem_row_major);
        __syncthreads();
#pragma unroll
        for (int it = 0; it < 8; it++) {
            int i = tid + it * 256;
            int r = i >> 6, c = i & 63;
            float v = su[r * 68 + c] + __half2float(sxw[r * 64 + c]);
            g_u[g][(size_t)(b0 + r) * 512 + n0 + c] = __cosf(v);
        }
        // ---- barrier 1: arrive, hide xw(t+1) prefetch behind spin
        __syncthreads();
        if (tid == 0) bar_arrive(ctr);
        if (t + 1 < T_STEPS) stage_xw(t + 1);
        if (tid == 0) bar_spin(ctr, 32u * (2u * t + 1u));
        __syncthreads();

        // ---- Phase B: scan + gates for batch row b
        float h0, h1;
        size_t gidx;
        {
            const int k = tid * 2;
            const int idx = b * 512 + k;
            float c0[4], c1[4], inc[4];
#pragma unroll
            for (int qq = 0; qq < 4; qq++) {
                float2 uv = *reinterpret_cast<const float2*>(&g_u[qq][idx]);
                c0[qq] = uv.x; c1[qq] = uv.y;
                inc[qq] = c0[qq] * c1[qq];
            }

#pragma unroll
            for (int o = 1; o < 32; o <<= 1) {
#pragma unroll
                for (int qq = 0; qq < 4; qq++) {
                    float up = __shfl_up_sync(0xffffffffu, inc[qq], o);
                    if (lane >= o) inc[qq] *= up;
                }
            }
            float exc[4];
#pragma unroll
            for (int qq = 0; qq < 4; qq++) {
                float up = __shfl_up_sync(0xffffffffu, inc[qq], 1);
                exc[qq] = (lane == 0) ? 1.0f : up;
            }
            if (lane == 31) {
#pragma unroll
                for (int qq = 0; qq < 4; qq++) swt[wid][qq] = inc[qq];
            }
            __syncthreads();
            float pre[4] = {1.f, 1.f, 1.f, 1.f};
            for (int w = 0; w < wid; w++) {
#pragma unroll
                for (int qq = 0; qq < 4; qq++) pre[qq] *= swt[w][qq];
            }

            float P0[4], P1[4];
#pragma unroll
            for (int qq = 0; qq < 4; qq++) {
                float e = pre[qq] * exc[qq];
                P0[qq] = e * c0[qq];
                P1[qq] = P0[qq] * c1[qq];
            }

            float f0 = fsig(P0[0]), f1 = fsig(P1[0]);
            float i0 = fsig(P0[1]), i1 = fsig(P1[1]);
            float u0 = ftanh(P0[2]), u1 = ftanh(P1[2]);
            float o0 = fsig(P0[3]), o1 = fsig(P1[3]);

            creg0 = f0 * creg0 + i0 * u0;
            creg1 = f1 * creg1 + i1 * u1;
            h0 = o0 * ftanh(creg0);
            h1 = o1 * ftanh(creg1);

            gidx = (size_t)b * 512 + k;
            *reinterpret_cast<__half2*>(&g_hf[gidx]) = __floats2half2_rn(h0, h1);
        }
        // ---- barrier 2: arrive (orders h), hide out[] stores behind spin
        __syncthreads();
        if (tid == 0) bar_arrive(ctr);
        *reinterpret_cast<float2*>(&out[(size_t)t * STATE_N + gidx]) = make_float2(h0, h1);
        if (t == T_STEPS - 1) {
            *reinterpret_cast<float2*>(&out[OUT_MAIN + gidx]) = make_float2(h0, h1);
            *reinterpret_cast<float2*>(&out[OUT_MAIN + STATE_N + gidx]) =
                make_float2(creg0, creg1);
        }
        if (tid == 0) bar_spin(ctr, 32u * (2u * t + 2u));
        __syncthreads();
    }
}

// ===========================================================================
extern "C" void kernel_launch(void* const* d_in, const int* in_sizes, int n_in,
                              void* d_out, int out_size) {
    const float* X = (const float*)d_in[0];
    GateParams gp;
    for (int g = 0; g < 4; g++) {
        gp.W[g]  = (const float*)d_in[1 + 3 * g];
        gp.b[g]  = (const float*)d_in[2 + 3 * g];
        gp.th[g] = (const float*)d_in[3 + 3 * g];
    }
    float* out = (float*)d_out;

    convert_x<<<(MTOT * 512 / 2) / 256, 256>>>(X);   // also inits g_hf / g_bar4
    convert_w<<<(4 * 512 * 1024 / 2) / 256, 256>>>(gp);

    const int p1_smem = 2 * P1_STAGE;   // 73728
    cudaFuncSetAttribute(phase1_wmma, cudaFuncAttributeMaxDynamicSharedMemorySize,
                         p1_smem);
    phase1_wmma<<<dim3(16, MTOT / 128), 256, p1_smem>>>(gp);

    recurrence_persistent<<<128, 256>>>(out);
}

// round 15
// speedup vs baseline: 1.0638x; 1.0440x over previous
#include <cuda_runtime.h>
#include <cuda_fp16.h>
#include <mma.h>
#include <math.h>
#include <stdint.h>

using namespace nvcuda;

// Problem constants
#define T_STEPS 256
#define BSZ     128
#define HID     512
#define MTOT    (T_STEPS * BSZ)                  // 32768
#define OUT_MAIN ((size_t)T_STEPS * BSZ * HID)   // 16777216
#define STATE_N  (BSZ * HID)                     // 65536

// ---------------------------------------------------------------------------
// Device scratch
// ---------------------------------------------------------------------------
__device__ __align__(256) __half g_xwh[4][(size_t)MTOT * 512];  // 128 MiB (fp16)
__device__ __align__(256) __half g_uh[4][STATE_N];              // cos values, fp16
__device__ __align__(256) __half g_hf[STATE_N];                 // h state, fp16

__device__ __align__(256) __half g_Xf[(size_t)MTOT * 512];
__device__ __align__(256) __half g_Wxf[4][512 * 512];
__device__ __align__(256) __half g_Whf[4][512 * 512];
__device__ __align__(256) unsigned g_bar4[4 * 32];

struct GateParams {
    const float* W[4];
    const float* b[4];
    const float* th[4];
};

// ---------------------------------------------------------------------------
// Conversions (convert_x also performs state init)
// ---------------------------------------------------------------------------
__global__ __launch_bounds__(256) void convert_x(const float* __restrict__ X) {
    size_t i = ((size_t)blockIdx.x * blockDim.x + threadIdx.x) * 2;
    float2 v = *reinterpret_cast<const float2*>(X + i);
    *reinterpret_cast<__half2*>(&g_Xf[i]) = __floats2half2_rn(v.x, v.y);

    size_t j = (size_t)blockIdx.x * blockDim.x + threadIdx.x;
    if (j < STATE_N)
        *reinterpret_cast<__half2*>(&g_hf[j * 2]) = __floats2half2_rn(0.f, 0.f);
    if (j < 4 * 32) g_bar4[j] = 0u;
}

__global__ __launch_bounds__(256) void convert_w(GateParams gp) {
    size_t i = ((size_t)blockIdx.x * blockDim.x + threadIdx.x) * 2;
    int g = (int)(i >> 19);
    size_t r = i & 524287;
    int n = (int)(r >> 10), k = (int)(r & 1023);
    float2 v = *reinterpret_cast<const float2*>(gp.W[g] + (size_t)n * 1024 + k);
    __half2 h = __floats2half2_rn(v.x, v.y);
    if (k < 512)
        *reinterpret_cast<__half2*>(&g_Wxf[g][(size_t)n * 512 + k]) = h;
    else
        *reinterpret_cast<__half2*>(&g_Whf[g][(size_t)n * 512 + (k - 512)]) = h;
}

// ===========================================================================
// Phase 1 (converged config): fp16 WMMA, 128x128 tile, K-chunk 64, 2-stage.
// ===========================================================================
#define SSTR1 72
#define P1_STAGE 36864
#define ESTR 132

__global__ __launch_bounds__(256) void phase1_wmma(GateParams gp) {
    extern __shared__ __align__(16) char smraw[];

    const int tid = threadIdx.x, wid = tid >> 5;
    const int nt = blockIdx.x;
    const int g  = nt >> 2;
    const int n0 = (nt & 3) * 128;
    const int m0 = blockIdx.y * 128;
    const int wm = wid >> 1;
    const int wn = wid & 1;

    const uint32_t smaddr = (uint32_t)__cvta_generic_to_shared(smraw);

    auto stage = [&](int c) {
        const int k0 = c * 64;
        const uint32_t base = smaddr + (uint32_t)(c & 1) * P1_STAGE;
#pragma unroll
        for (int it = 0; it < 8; it++) {
            int i = tid + it * 256;
            int mat = i >> 10;
            int r = (i >> 3) & 127, s = i & 7;
            const __half* src = mat
                ? &g_Wxf[g][(size_t)(n0 + r) * 512 + k0 + s * 8]
                : &g_Xf[(size_t)(m0 + r) * 512 + k0 + s * 8];
            asm volatile("cp.async.cg.shared.global [%0], [%1], 16;"
                :: "r"(base + (uint32_t)mat * 18432 + (uint32_t)(r * SSTR1 + s * 8) * 2),
                   "l"(src) : "memory");
        }
        asm volatile("cp.async.commit_group;" ::: "memory");
    };

    wmma::fragment<wmma::accumulator, 16, 16, 16, float> acc[2][4];
#pragma unroll
    for (int i = 0; i < 2; i++)
#pragma unroll
        for (int j = 0; j < 4; j++) wmma::fill_fragment(acc[i][j], 0.0f);

    stage(0);
    for (int c = 0; c < 8; c++) {
        if (c < 7) {
            stage(c + 1);
            asm volatile("cp.async.wait_group 1;" ::: "memory");
        } else {
            asm volatile("cp.async.wait_group 0;" ::: "memory");
        }
        __syncthreads();
        const __half* sA = reinterpret_cast<const __half*>(smraw + (c & 1) * P1_STAGE);
        const __half* sB = sA + 128 * SSTR1;
#pragma unroll
        for (int kk = 0; kk < 64; kk += 16) {
            wmma::fragment<wmma::matrix_a, 16, 16, 16, __half, wmma::row_major> a[2];
            wmma::fragment<wmma::matrix_b, 16, 16, 16, __half, wmma::col_major> bfr[4];
#pragma unroll
            for (int i = 0; i < 2; i++)
                wmma::load_matrix_sync(a[i], &sA[(wm * 32 + i * 16) * SSTR1 + kk], SSTR1);
#pragma unroll
            for (int j = 0; j < 4; j++)
                wmma::load_matrix_sync(bfr[j], &sB[(wn * 64 + j * 16) * SSTR1 + kk], SSTR1);
#pragma unroll
            for (int i = 0; i < 2; i++)
#pragma unroll
                for (int j = 0; j < 4; j++)
                    wmma::mma_sync(acc[i][j], a[i], bfr[j], acc[i][j]);
        }
        __syncthreads();
    }

    float* smf = reinterpret_cast<float*>(smraw);
#pragma unroll
    for (int i = 0; i < 2; i++)
#pragma unroll
        for (int j = 0; j < 4; j++)
            wmma::store_matrix_sync(&smf[(wm * 32 + i * 16) * ESTR + wn * 64 + j * 16],
                                    acc[i][j], ESTR, wmma::mem_row_major);
    __syncthreads();
    const float* __restrict__ bb = gp.b[g];
    const float* __restrict__ tt = gp.th[g];
#pragma unroll
    for (int it = 0; it < 16; it++) {
        int i = tid + it * 256;
        int r = i >> 5, c = (i & 31) * 4;
        int n = n0 + c;
        float4 v = *reinterpret_cast<const float4*>(&smf[r * ESTR + c]);
        v.x += bb[n + 0] + tt[n + 0]; v.y += bb[n + 1] + tt[n + 1];
        v.z += bb[n + 2] + tt[n + 2]; v.w += bb[n + 3] + tt[n + 3];
        __half2 h01 = __floats2half2_rn(v.x, v.y);
        __half2 h23 = __floats2half2_rn(v.z, v.w);
        uint2 packed = make_uint2(*reinterpret_cast<uint32_t*>(&h01),
                                  *reinterpret_cast<uint32_t*>(&h23));
        *reinterpret_cast<uint2*>(&g_xwh[g][(size_t)(m0 + r) * 512 + n]) = packed;
    }
}

// ===========================================================================
// Persistent recurrence: all-thread acquire-spin barriers, fp16 u.
// ===========================================================================
#define HSTR 520

__device__ __forceinline__ void bar_arrive(unsigned* ctr) {
    asm volatile("red.release.gpu.global.add.u32 [%0], %1;"
                 :: "l"(ctr), "r"(1u) : "memory");
}
__device__ __forceinline__ void bar_spin(unsigned* ctr, unsigned target) {
    unsigned v;
    do {
        asm volatile("ld.acquire.gpu.global.u32 %0, [%1];"
                     : "=r"(v) : "l"(ctr) : "memory");
    } while (v < target);
}

__device__ __forceinline__ float fsig(float x) {
    float t = __expf(-x);
    return __fdividef(1.0f, 1.0f + t);
}
__device__ __forceinline__ float ftanh(float x) {
    float t = __expf(-2.0f * x);
    return __fdividef(1.0f - t, 1.0f + t);
}

__global__ __launch_bounds__(256, 1) void recurrence_persistent(float* __restrict__ out) {
    __shared__ __align__(16) __half sH[32 * HSTR];     // 33280 B
    __shared__ __align__(16) float su[32 * 68];        // 8704 B
    __shared__ __align__(16) __half sxw[32 * 64];      // 4096 B
    __shared__ float swt[8][4];

    const int tid = threadIdx.x, wid = tid >> 5, lane = tid & 31;
    const int cta = blockIdx.x;
    const int q   = cta >> 5;
    const int within = cta & 31;
    const int g  = within >> 3;
    const int nt = within & 7;
    const int n0 = nt * 64;
    const int b0 = q * 32;
    const int wm = wid & 1;
    const int wn = wid >> 1;
    const int b = cta;
    unsigned* ctr = &g_bar4[q * 32];

    const uint32_t sH_addr  = (uint32_t)__cvta_generic_to_shared(sH);
    const uint32_t sxw_addr = (uint32_t)__cvta_generic_to_shared(sxw);

    float creg0 = 0.f, creg1 = 0.f;

    // ---- Preload Wh fragments into registers (2 halves through sH) ----
    wmma::fragment<wmma::matrix_b, 16, 16, 16, __half, wmma::col_major> bfr[32];
#pragma unroll
    for (int half = 0; half < 2; half++) {
        __syncthreads();
#pragma unroll
        for (int it = 0; it < 8; it++) {
            int i = tid + it * 256;
            int r = i >> 6, s = i & 63;
            *reinterpret_cast<uint4*>(reinterpret_cast<char*>(sH) + (r * HSTR + s * 8) * 2) =
                *reinterpret_cast<const uint4*>(&g_Whf[g][(size_t)(n0 + half * 32 + r) * 512 + s * 8]);
        }
        __syncthreads();
        if ((wn >> 1) == half) {
            const int rloc = (wn & 1) * 16;
#pragma unroll
            for (int kk = 0; kk < 32; kk++)
                wmma::load_matrix_sync(bfr[kk], &sH[rloc * HSTR + kk * 16], HSTR);
        }
    }
    __syncthreads();

    auto stage_xw = [&](int t) {
        {
            int r = tid >> 3, s = tid & 7;
            const __half* src = &g_xwh[g][((size_t)t * BSZ + b0 + r) * 512 + n0 + s * 8];
            asm volatile("cp.async.cg.shared.global [%0], [%1], 16;"
                :: "r"(sxw_addr + (uint32_t)(r * 64 + s * 8) * 2), "l"(src) : "memory");
        }
        asm volatile("cp.async.commit_group;" ::: "memory");
    };

    stage_xw(0);

    for (int t = 0; t < T_STEPS; t++) {
        // ---- stage h tile in 2 K-halves
#pragma unroll
        for (int half = 0; half < 2; half++) {
#pragma unroll
            for (int it = 0; it < 4; it++) {
                int i = tid + it * 256;
                int r = i >> 5, s = (i & 31) + half * 32;
                const __half* src = &g_hf[(size_t)(b0 + r) * 512 + s * 8];
                asm volatile("cp.async.cg.shared.global [%0], [%1], 16;"
                    :: "r"(sH_addr + (uint32_t)(r * HSTR + s * 8) * 2), "l"(src) : "memory");
            }
            asm volatile("cp.async.commit_group;" ::: "memory");
        }

        wmma::fragment<wmma::accumulator, 16, 16, 16, float> acc0, acc1;
        wmma::fill_fragment(acc0, 0.0f);
        wmma::fill_fragment(acc1, 0.0f);

        asm volatile("cp.async.wait_group 1;" ::: "memory");
        __syncthreads();
#pragma unroll
        for (int kk = 0; kk < 16; kk += 2) {
            wmma::fragment<wmma::matrix_a, 16, 16, 16, __half, wmma::row_major> a0, a1;
            wmma::load_matrix_sync(a0, &sH[(wm * 16) * HSTR + kk * 16], HSTR);
            wmma::load_matrix_sync(a1, &sH[(wm * 16) * HSTR + (kk + 1) * 16], HSTR);
            wmma::mma_sync(acc0, a0, bfr[kk], acc0);
            wmma::mma_sync(acc1, a1, bfr[kk + 1], acc1);
        }
        asm volatile("cp.async.wait_group 0;" ::: "memory");
        __syncthreads();
#pragma unroll
        for (int kk = 16; kk < 32; kk += 2) {
            wmma::fragment<wmma::matrix_a, 16, 16, 16, __half, wmma::row_major> a0, a1;
            wmma::load_matrix_sync(a0, &sH[(wm * 16) * HSTR + kk * 16], HSTR);
            wmma::load_matrix_sync(a1, &sH[(wm * 16) * HSTR + (kk + 1) * 16], HSTR);
            wmma::mma_sync(acc0, a0, bfr[kk], acc0);
            wmma::mma_sync(acc1, a1, bfr[kk + 1], acc1);
        }
#pragma unroll
        for (int e = 0; e < acc0.num_elements; e++) acc0.x[e] += acc1.x[e];

        // ---- epilogue: u = cos(xw + hv) -> fp16, half2 stores
        wmma::store_matrix_sync(&su[(wm * 16) * 68 + wn * 16], acc0, 68,
                                wmma::mem_row_major);
        __syncthreads();
#pragma unroll
        for (int it = 0; it < 4; it++) {
            int i = tid + it * 256;             // 0..1023 (pairs)
            int r = i >> 5, c2 = (i & 31) * 2;
            float v0 = su[r * 68 + c2]     + __half2float(sxw[r * 64 + c2]);
            float v1 = su[r * 68 + c2 + 1] + __half2float(sxw[r * 64 + c2 + 1]);
            *reinterpret_cast<__half2*>(&g_uh[g][(size_t)(b0 + r) * 512 + n0 + c2]) =
                __floats2half2_rn(__cosf(v0), __cosf(v1));
        }
        // ---- barrier 1: tid0 arrives; all threads stage xw(t+1) then spin
        __syncthreads();
        if (tid == 0) bar_arrive(ctr);
        if (t + 1 < T_STEPS) stage_xw(t + 1);
        bar_spin(ctr, 32u * (2u * t + 1u));

        // ---- Phase B: scan + gates for batch row b
        float h0, h1;
        size_t gidx;
        {
            const int k = tid * 2;
            const int idx = b * 512 + k;
            float c0[4], c1[4], inc[4];
#pragma unroll
            for (int qq = 0; qq < 4; qq++) {
                __half2 uv = *reinterpret_cast<const __half2*>(&g_uh[qq][idx]);
                float2 uf = __half22float2(uv);
                c0[qq] = uf.x; c1[qq] = uf.y;
                inc[qq] = c0[qq] * c1[qq];
            }

#pragma unroll
            for (int o = 1; o < 32; o <<= 1) {
#pragma unroll
                for (int qq = 0; qq < 4; qq++) {
                    float up = __shfl_up_sync(0xffffffffu, inc[qq], o);
                    if (lane >= o) inc[qq] *= up;
                }
            }
            float exc[4];
#pragma unroll
            for (int qq = 0; qq < 4; qq++) {
                float up = __shfl_up_sync(0xffffffffu, inc[qq], 1);
                exc[qq] = (lane == 0) ? 1.0f : up;
            }
            if (lane == 31) {
#pragma unroll
                for (int qq = 0; qq < 4; qq++) swt[wid][qq] = inc[qq];
            }
            __syncthreads();
            float pre[4] = {1.f, 1.f, 1.f, 1.f};
            for (int w = 0; w < wid; w++) {
#pragma unroll
                for (int qq = 0; qq < 4; qq++) pre[qq] *= swt[w][qq];
            }

            float P0[4], P1[4];
#pragma unroll
            for (int qq = 0; qq < 4; qq++) {
                float e = pre[qq] * exc[qq];
                P0[qq] = e * c0[qq];
                P1[qq] = P0[qq] * c1[qq];
            }

            float f0 = fsig(P0[0]), f1 = fsig(P1[0]);
            float i0 = fsig(P0[1]), i1 = fsig(P1[1]);
            float u0 = ftanh(P0[2]), u1 = ftanh(P1[2]);
            float o0 = fsig(P0[3]), o1 = fsig(P1[3]);

            creg0 = f0 * creg0 + i0 * u0;
            creg1 = f1 * creg1 + i1 * u1;
            h0 = o0 * ftanh(creg0);
            h1 = o1 * ftanh(creg1);

            gidx = (size_t)b * 512 + k;
            *reinterpret_cast<__half2*>(&g_hf[gidx]) = __floats2half2_rn(h0, h1);
        }
        // ---- barrier 2: tid0 arrives; out[] stores hidden; all threads spin
        __syncthreads();
        if (tid == 0) bar_arrive(ctr);
        *reinterpret_cast<float2*>(&out[(size_t)t * STATE_N + gidx]) = make_float2(h0, h1);
        if (t == T_STEPS - 1) {
            *reinterpret_cast<float2*>(&out[OUT_MAIN + gidx]) = make_float2(h0, h1);
            *reinterpret_cast<float2*>(&out[OUT_MAIN + STATE_N + gidx]) =
                make_float2(creg0, creg1);
        }
        bar_spin(ctr, 32u * (2u * t + 2u));
    }
}

// ===========================================================================
extern "C" void kernel_launch(void* const* d_in, const int* in_sizes, int n_in,
                              void* d_out, int out_size) {
    const float* X = (const float*)d_in[0];
    GateParams gp;
    for (int g = 0; g < 4; g++) {
        gp.W[g]  = (const float*)d_in[1 + 3 * g];
        gp.b[g]  = (const float*)d_in[2 + 3 * g];
        gp.th[g] = (const float*)d_in[3 + 3 * g];
    }
    float* out = (float*)d_out;

    convert_x<<<(MTOT * 512 / 2) / 256, 256>>>(X);   // also inits g_hf / g_bar4
    convert_w<<<(4 * 512 * 1024 / 2) / 256, 256>>>(gp);

    const int p1_smem = 2 * P1_STAGE;   // 73728
    cudaFuncSetAttribute(phase1_wmma, cudaFuncAttributeMaxDynamicSharedMemorySize,
                         p1_smem);
    phase1_wmma<<<dim3(16, MTOT / 128), 256, p1_smem>>>(gp);

    recurrence_persistent<<<128, 256>>>(out);
}